// round 15
// baseline (speedup 1.0000x reference)
#include <cuda_runtime.h>
#include <cuda_fp16.h>
#include <cstdint>

// ---------------- Problem constants ----------------
constexpr int NN = 16384;   // nodes per level
constexpr int DD = 256;     // feature dim
constexpr int KP = 16;      // in-degree
constexpr int LL = 16;      // levels

// ---------------- Fused-level tiling (fp16 operands, fp32 accum) ----------------
// CTA: 256 threads = 8 warps (2m x 4n), warp tile 32x64. BM=64, BN=256, BK=64.
// SMEM 110592 B -> 2 CTAs/SM: gather of one CTA overlaps GEMM of the other.
constexpr int THREADS = 256;
constexpr int BM = 64, BN = 256, BK = 64;
constexpr int NCH = DD / BK;                    // 4 K-chunks per GEMM
constexpr int PADH = 72;                        // halves per SMEM row (144B, conflict-free)
constexpr int ACH = BM * PADH;                  // 4608 halves : one A/MSG chunk buffer
constexpr int BCH = BN * PADH;                  // 18432 halves: one B stage
constexpr int MSGH = NCH * ACH;                 // 18432 halves: 4 A chunk buffers
constexpr int BOFF = MSGH;
constexpr int BSTAGES = 2;
constexpr int SMEM_BYTES = (MSGH + BSTAGES * BCH) * 2;   // 110592 B

// ---------------- Scratch ----------------
__device__ __half g_Ha[NN * DD];
__device__ __half g_Hb[NN * DD];
__device__ __half g_W1h[DD * DD];
__device__ __half g_W2h[DD * DD];

// ---------------- Portable PTX helpers ----------------
__device__ __forceinline__ uint32_t smem_u32(const void* p) {
    uint32_t a;
    asm("{ .reg .u64 t; cvta.to.shared.u64 t, %1; cvt.u32.u64 %0, t; }" : "=r"(a) : "l"(p));
    return a;
}
__device__ __forceinline__ void cp16(uint32_t dst, const void* src) {
    asm volatile("cp.async.cg.shared.global [%0], [%1], 16;" :: "r"(dst), "l"(src));
}
#define CP_COMMIT() asm volatile("cp.async.commit_group;" ::: "memory")
#define CP_WAIT(n)  asm volatile("cp.async.wait_group %0;" :: "n"(n) : "memory")

__device__ __forceinline__ void ldsm4(uint32_t& r0, uint32_t& r1, uint32_t& r2, uint32_t& r3,
                                      uint32_t addr) {
    asm volatile("ldmatrix.sync.aligned.m8n8.x4.shared.b16 {%0,%1,%2,%3}, [%4];"
                 : "=r"(r0), "=r"(r1), "=r"(r2), "=r"(r3) : "r"(addr));
}
__device__ __forceinline__ void mma_f16(float* c, uint32_t a0, uint32_t a1, uint32_t a2,
                                        uint32_t a3, uint32_t b0, uint32_t b1) {
    asm volatile("mma.sync.aligned.m16n8k16.row.col.f32.f16.f16.f32 "
                 "{%0,%1,%2,%3}, {%4,%5,%6,%7}, {%8,%9}, {%0,%1,%2,%3};"
                 : "+f"(c[0]), "+f"(c[1]), "+f"(c[2]), "+f"(c[3])
                 : "r"(a0), "r"(a1), "r"(a2), "r"(a3), "r"(b0), "r"(b1));
}

// ================= Fused level kernel =================
// MODE 0: A = fp16(x0 rows)   MODE 1: A = fp16(relu(mean_p Hprev[idx_p]+b2)+xl); y->yout
// Then MSG = relu(A @ W1h^T + b1) (SMEM), Hout = MSG @ W2h^T (fp16 GMEM).
template<int MODE>
__global__ __launch_bounds__(THREADS, 2) void fused_level(
    const float* __restrict__ x0,
    const __half* __restrict__ Hprev, const int* __restrict__ idx,
    const float* __restrict__ b2, const float* __restrict__ xl,
    float* __restrict__ yout,
    const __half* __restrict__ W1h, const float* __restrict__ b1,
    const __half* __restrict__ W2h, __half* __restrict__ Hout)
{
    extern __shared__ __half smh[];
    const uint32_t smb = smem_u32(smh);

    const int tid = threadIdx.x;
    const int lane = tid & 31, wid = tid >> 5;
    const int g = lane >> 2, t = lane & 3;
    const int wm = (wid & 1) * 32;           // 2 m-warps
    const int wn = (wid >> 1) * 64;          // 4 n-warps
    const int bm = blockIdx.x * BM;

    // ---- weight cp.async mapping: 256 rows x 8x16B = 2048 xfers, 8/thread ----
    const int ar0 = tid >> 3, av0 = tid & 7;            // ar0 in [0,32)
    auto issueBchunk = [&](int chunk, int stage) {      // chunk 0-3: W1, 4-7: W2
        const __half* W = (chunk < 4) ? W1h : W2h;
        const __half* src = W + (size_t)ar0 * DD + (chunk & 3) * BK + av0 * 8;
        const uint32_t dst = smb + (uint32_t)(BOFF + stage * BCH + ar0 * PADH + av0 * 8) * 2u;
        #pragma unroll
        for (int i = 0; i < 8; i++)                     // rows ar0 + i*32
            cp16(dst + (uint32_t)(i * 32 * PADH) * 2u, src + (size_t)(i * 32) * DD);
        CP_COMMIT();
    };

    // Kick W1 chunks 0,1 so they land during the prologue.
    issueBchunk(0, 0);
    issueBchunk(1, 1);

    // ================= Prologue: build A (fp16) in MSG buffers =================
    if (MODE == 0) {
        // convert x0 rows [bm, bm+64): 64 rows x 16 col-units / 256 thr = 4 passes
        #pragma unroll
        for (int pass = 0; pass < 4; pass++) {
            const int e = tid + pass * 256;             // 0..1023
            const int rr = e >> 4, co = (e & 15) * 16;
            const float4* xs = (const float4*)(x0 + (size_t)(bm + rr) * DD + co);
            uint4 hv[2];
            #pragma unroll
            for (int h = 0; h < 2; h++) {
                float4 v0 = xs[h * 2], v1 = xs[h * 2 + 1];
                __half2* hq = (__half2*)&hv[h];
                hq[0] = __float22half2_rn(make_float2(v0.x, v0.y));
                hq[1] = __float22half2_rn(make_float2(v0.z, v0.w));
                hq[2] = __float22half2_rn(make_float2(v1.x, v1.y));
                hq[3] = __float22half2_rn(make_float2(v1.z, v1.w));
            }
            const int ch = co >> 6, kcol = co & 63;
            *(uint4*)(smh + ch * ACH + rr * PADH + kcol) = hv[0];
            *(uint4*)(smh + ch * ACH + rr * PADH + kcol + 8) = hv[1];
        }
    } else {
        // gather: 4 threads per node, each owns an 8-col slice per (chunk, half)
        const int r = tid >> 2, q = tid & 3;            // r in [0,64)
        const int node = bm + r;
        const int4* ip = (const int4*)(idx + (size_t)node * KP);
        int pr[KP];
        #pragma unroll
        for (int i = 0; i < 4; i++) {
            int4 v = ip[i];
            pr[i*4+0] = v.x; pr[i*4+1] = v.y; pr[i*4+2] = v.z; pr[i*4+3] = v.w;
        }
        const float inv = 1.0f / (float)KP;
        #pragma unroll
        for (int ch = 0; ch < 4; ch++) {
            #pragma unroll
            for (int h = 0; h < 2; h++) {
                const int gc = ch * 64 + h * 32 + q * 8;
                float s[8] = {};
                #pragma unroll
                for (int p = 0; p < KP; p++) {
                    uint4 u = *(const uint4*)(Hprev + (size_t)pr[p] * DD + gc);
                    const __half2* hp = (const __half2*)&u;
                    #pragma unroll
                    for (int j = 0; j < 4; j++) {
                        float2 f = __half22float2(hp[j]);
                        s[2*j]   += f.x;
                        s[2*j+1] += f.y;
                    }
                }
                float4 bb0 = *(const float4*)(b2 + gc);
                float4 bb1 = *(const float4*)(b2 + gc + 4);
                float4 xx0 = *(const float4*)(xl + (size_t)node * DD + gc);
                float4 xx1 = *(const float4*)(xl + (size_t)node * DD + gc + 4);
                float o[8];
                o[0] = fmaxf(s[0]*inv + bb0.x, 0.f) + xx0.x;
                o[1] = fmaxf(s[1]*inv + bb0.y, 0.f) + xx0.y;
                o[2] = fmaxf(s[2]*inv + bb0.z, 0.f) + xx0.z;
                o[3] = fmaxf(s[3]*inv + bb0.w, 0.f) + xx0.w;
                o[4] = fmaxf(s[4]*inv + bb1.x, 0.f) + xx1.x;
                o[5] = fmaxf(s[5]*inv + bb1.y, 0.f) + xx1.y;
                o[6] = fmaxf(s[6]*inv + bb1.z, 0.f) + xx1.z;
                o[7] = fmaxf(s[7]*inv + bb1.w, 0.f) + xx1.w;
                float4* yo = (float4*)(yout + (size_t)node * DD + gc);
                yo[0] = make_float4(o[0], o[1], o[2], o[3]);
                yo[1] = make_float4(o[4], o[5], o[6], o[7]);
                uint4 hv;
                __half2* hq = (__half2*)&hv;
                hq[0] = __float22half2_rn(make_float2(o[0], o[1]));
                hq[1] = __float22half2_rn(make_float2(o[2], o[3]));
                hq[2] = __float22half2_rn(make_float2(o[4], o[5]));
                hq[3] = __float22half2_rn(make_float2(o[6], o[7]));
                *(uint4*)(smh + ch * ACH + r * PADH + (h * 32 + q * 8)) = hv;
            }
        }
    }

    // ---- ldmatrix lane mappings ----
    const int arow = lane & 15;
    const int acol = (lane >> 4) * 8;
    const int brow = (lane & 7) + ((lane >> 4) << 3);
    const int bcol = ((lane >> 3) & 1) * 8;
    uint32_t a_off[2], b_off[4];
    #pragma unroll
    for (int mf = 0; mf < 2; mf++)
        a_off[mf] = (uint32_t)((wm + mf * 16 + arow) * PADH + acol) * 2u;
    #pragma unroll
    for (int np = 0; np < 4; np++)
        b_off[np] = (uint32_t)(BOFF + (wn + np * 16 + brow) * PADH + bcol) * 2u;

    float acc[2][8][4] = {};

    auto compute = [&](int akc, int stage) {
        const uint32_t abase = smb + (uint32_t)(akc * ACH) * 2u;
        const uint32_t bbase = smb + (uint32_t)(stage * BCH) * 2u;
        #pragma unroll
        for (int ks = 0; ks < 4; ks++) {
            const uint32_t ko = ks * 32u;
            uint32_t a[2][4], b[4][4];
            #pragma unroll
            for (int mf = 0; mf < 2; mf++)
                ldsm4(a[mf][0], a[mf][1], a[mf][2], a[mf][3], abase + a_off[mf] + ko);
            #pragma unroll
            for (int np = 0; np < 4; np++)
                ldsm4(b[np][0], b[np][1], b[np][2], b[np][3], bbase + b_off[np] + ko);
            #pragma unroll
            for (int mf = 0; mf < 2; mf++)
                #pragma unroll
                for (int nf = 0; nf < 8; nf++)
                    mma_f16(acc[mf][nf],
                            a[mf][0], a[mf][1], a[mf][2], a[mf][3],
                            b[nf >> 1][(nf & 1) * 2], b[nf >> 1][(nf & 1) * 2 + 1]);
        }
    };

    // ================= Phase 1: MSG = relu(A @ W1 + b1) =================
    // 2-stage weight ring: wait, sync, compute, sync, reissue.
    #pragma unroll
    for (int kc = 0; kc < NCH; kc++) {
        if (kc < NCH - 1) { CP_WAIT(1); } else { CP_WAIT(0); }
        __syncthreads();
        compute(kc, kc & 1);
        __syncthreads();
        if (kc + 2 < NCH) issueBchunk(kc + 2, kc & 1);
        else if (kc + 2 < 8) issueBchunk(kc + 2, kc & 1);   // W2 chunks 0,1
    }

    // Phase-1 epilogue: relu(acc + b1) -> MSG buffers as fp16 (A-operand layout)
    #pragma unroll
    for (int mf = 0; mf < 2; mf++) {
        const int r0 = wm + mf * 16 + g;
        #pragma unroll
        for (int nf = 0; nf < 8; nf++) {
            const int col = wn + nf * 8 + 2 * t;
            const int ch = col >> 6, kcol = col & 63;
            float2 bb = *(const float2*)(b1 + col);
            float2 v0, v1;
            v0.x = fmaxf(acc[mf][nf][0] + bb.x, 0.f);
            v0.y = fmaxf(acc[mf][nf][1] + bb.y, 0.f);
            v1.x = fmaxf(acc[mf][nf][2] + bb.x, 0.f);
            v1.y = fmaxf(acc[mf][nf][3] + bb.y, 0.f);
            *(__half2*)(smh + ch * ACH + r0 * PADH + kcol) = __float22half2_rn(v0);
            *(__half2*)(smh + ch * ACH + (r0 + 8) * PADH + kcol) = __float22half2_rn(v1);
            acc[mf][nf][0] = 0.f; acc[mf][nf][1] = 0.f;
            acc[mf][nf][2] = 0.f; acc[mf][nf][3] = 0.f;
        }
    }

    // ================= Phase 2: H = MSG @ W2 =================
    #pragma unroll
    for (int kc = 0; kc < NCH; kc++) {
        if (kc < NCH - 1) { CP_WAIT(1); } else { CP_WAIT(0); }
        __syncthreads();                     // publishes MSG writes (kc==0)
        compute(kc, kc & 1);
        __syncthreads();
        if (kc + 2 < NCH) issueBchunk(kc + 6, kc & 1);      // W2 chunks 2,3
    }

    // Phase-2 epilogue: H to GMEM as fp16
    #pragma unroll
    for (int mf = 0; mf < 2; mf++) {
        const int r0 = bm + wm + mf * 16 + g;
        #pragma unroll
        for (int nf = 0; nf < 8; nf++) {
            const int col = wn + nf * 8 + 2 * t;
            float2 v0, v1;
            v0.x = acc[mf][nf][0]; v0.y = acc[mf][nf][1];
            v1.x = acc[mf][nf][2]; v1.y = acc[mf][nf][3];
            *(__half2*)(Hout + (size_t)r0 * DD + col) = __float22half2_rn(v0);
            *(__half2*)(Hout + (size_t)(r0 + 8) * DD + col) = __float22half2_rn(v1);
        }
    }
}

// ------- Final gather: y = relu(mean_p H[idx_p] + b2) + x -------
__global__ __launch_bounds__(256) void gather_epi(
    const __half* __restrict__ H, const int* __restrict__ idx,
    const float* __restrict__ b2, const float* __restrict__ x,
    float* __restrict__ y)
{
    const int node = blockIdx.x * 8 + (threadIdx.x >> 5);
    const int co = (threadIdx.x & 31) * 8;
    const int4* ip = (const int4*)(idx + (size_t)node * KP);

    int pr[KP];
    #pragma unroll
    for (int i = 0; i < 4; i++) {
        int4 v = ip[i];
        pr[i*4+0] = v.x; pr[i*4+1] = v.y; pr[i*4+2] = v.z; pr[i*4+3] = v.w;
    }
    float s[8] = {};
    #pragma unroll
    for (int p = 0; p < KP; p++) {
        uint4 u = *(const uint4*)(H + (size_t)pr[p] * DD + co);
        const __half2* hp = (const __half2*)&u;
        #pragma unroll
        for (int j = 0; j < 4; j++) {
            float2 f = __half22float2(hp[j]);
            s[j*2]   += f.x;
            s[j*2+1] += f.y;
        }
    }
    const float inv = 1.0f / (float)KP;
    float4 bb0 = *(const float4*)(b2 + co);
    float4 bb1 = *(const float4*)(b2 + co + 4);
    float4 xx0 = *(const float4*)(x + (size_t)node * DD + co);
    float4 xx1 = *(const float4*)(x + (size_t)node * DD + co + 4);
    float4* yo = (float4*)(y + (size_t)node * DD + co);
    yo[0] = make_float4(fmaxf(s[0]*inv + bb0.x, 0.f) + xx0.x,
                        fmaxf(s[1]*inv + bb0.y, 0.f) + xx0.y,
                        fmaxf(s[2]*inv + bb0.z, 0.f) + xx0.z,
                        fmaxf(s[3]*inv + bb0.w, 0.f) + xx0.w);
    yo[1] = make_float4(fmaxf(s[4]*inv + bb1.x, 0.f) + xx1.x,
                        fmaxf(s[5]*inv + bb1.y, 0.f) + xx1.y,
                        fmaxf(s[6]*inv + bb1.z, 0.f) + xx1.z,
                        fmaxf(s[7]*inv + bb1.w, 0.f) + xx1.w);
}

// ------- 256x256 transpose + fp16 rna -------
__global__ void transpose256h(const float* __restrict__ W, __half* __restrict__ Wt) {
    __shared__ float tbuf[32][33];
    const int bx = (blockIdx.x & 7) * 32;
    const int by = (blockIdx.x >> 3) * 32;
    const int x = threadIdx.x, y = threadIdx.y;
    #pragma unroll
    for (int i = 0; i < 32; i += 8)
        tbuf[y + i][x] = W[(by + y + i) * DD + bx + x];
    __syncthreads();
    #pragma unroll
    for (int i = 0; i < 32; i += 8)
        Wt[(bx + y + i) * DD + by + x] = __float2half_rn(tbuf[x][y + i]);
}

// ---------------- Launch ----------------
extern "C" void kernel_launch(void* const* d_in, const int* in_sizes, int n_in,
                              void* d_out, int out_size)
{
    const float* x   = (const float*)d_in[0];
    const int*   idx = (const int*)  d_in[1];
    const float* W1  = (const float*)d_in[2];
    const float* b1  = (const float*)d_in[3];
    const float* W2  = (const float*)d_in[4];
    const float* b2  = (const float*)d_in[5];
    float* out = (float*)d_out;

    __half *Ha, *Hb, *w1h, *w2h;
    cudaGetSymbolAddress((void**)&Ha,  g_Ha);
    cudaGetSymbolAddress((void**)&Hb,  g_Hb);
    cudaGetSymbolAddress((void**)&w1h, g_W1h);
    cudaGetSymbolAddress((void**)&w2h, g_W2h);

    cudaFuncSetAttribute(fused_level<0>, cudaFuncAttributeMaxDynamicSharedMemorySize, SMEM_BYTES);
    cudaFuncSetAttribute(fused_level<1>, cudaFuncAttributeMaxDynamicSharedMemorySize, SMEM_BYTES);

    const size_t lvl = (size_t)NN * DD;

    transpose256h<<<64, dim3(32, 8)>>>(W1, w1h);
    transpose256h<<<64, dim3(32, 8)>>>(W2, w2h);

    cudaMemcpyAsync(out, x, lvl * sizeof(float), cudaMemcpyDeviceToDevice);

    const int grid = NN / BM;   // 256 CTAs, one wave at 2 CTAs/SM

    __half* Hbuf[2] = {Ha, Hb};

    fused_level<0><<<grid, THREADS, SMEM_BYTES>>>(
        x, nullptr, nullptr, nullptr, nullptr, nullptr, w1h, b1, w2h, Hbuf[0]);

    for (int l = 1; l <= 14; l++) {
        fused_level<1><<<grid, THREADS, SMEM_BYTES>>>(
            nullptr, Hbuf[(l - 1) & 1], idx + (size_t)(l - 1) * NN * KP,
            b2, x + (size_t)l * lvl, out + (size_t)l * lvl,
            w1h, b1, w2h, Hbuf[l & 1]);
    }

    gather_epi<<<NN / 8, 256>>>(Hbuf[14 & 1], idx + (size_t)14 * NN * KP, b2,
                                x + (size_t)15 * lvl, out + (size_t)15 * lvl);
}

// round 16
// speedup vs baseline: 1.1475x; 1.1475x over previous
#include <cuda_runtime.h>
#include <cuda_fp16.h>
#include <cstdint>

// ---------------- Problem constants ----------------
constexpr int NN = 16384;   // nodes per level
constexpr int DD = 256;     // feature dim
constexpr int KP = 16;      // in-degree
constexpr int LL = 16;      // levels

// ---------------- Fused-level tiling (fp16 operands, fp32 accum) ----------------
// CTA: 512 threads = 16 warps (4m x 4n), warp tile 32x64. BM=128, BN=256, BK=64.
constexpr int THREADS = 512;
constexpr int BM = 128, BN = 256, BK = 64;
constexpr int NCH = DD / BK;                    // 4 K-chunks per GEMM
constexpr int PADH = 72;                        // halves per SMEM row (144B, conflict-free)
constexpr int ACH = BM * PADH;                  // one A/MSG chunk buffer (halves)
constexpr int BCH = BN * PADH;                  // one B stage (halves)
constexpr int MSGH = NCH * ACH;                 // 4 A chunk buffers
constexpr int BOFF = MSGH;
constexpr int BSTAGES = 3;
constexpr int SMEM_BYTES = (MSGH + BSTAGES * BCH) * 2;   // 184320 B

// ---------------- Scratch ----------------
__device__ __half g_Ha[NN * DD];
__device__ __half g_Hb[NN * DD];
__device__ __half g_W1h[DD * DD];
__device__ __half g_W2h[DD * DD];

// ---------------- Portable PTX helpers ----------------
__device__ __forceinline__ uint32_t smem_u32(const void* p) {
    uint32_t a;
    asm("{ .reg .u64 t; cvta.to.shared.u64 t, %1; cvt.u32.u64 %0, t; }" : "=r"(a) : "l"(p));
    return a;
}
__device__ __forceinline__ void cp16(uint32_t dst, const void* src) {
    asm volatile("cp.async.cg.shared.global [%0], [%1], 16;" :: "r"(dst), "l"(src));
}
#define CP_COMMIT() asm volatile("cp.async.commit_group;" ::: "memory")
#define CP_WAIT(n)  asm volatile("cp.async.wait_group %0;" :: "n"(n) : "memory")

__device__ __forceinline__ void ldsm4(uint32_t& r0, uint32_t& r1, uint32_t& r2, uint32_t& r3,
                                      uint32_t addr) {
    asm volatile("ldmatrix.sync.aligned.m8n8.x4.shared.b16 {%0,%1,%2,%3}, [%4];"
                 : "=r"(r0), "=r"(r1), "=r"(r2), "=r"(r3) : "r"(addr));
}
__device__ __forceinline__ void mma_f16(float* c, uint32_t a0, uint32_t a1, uint32_t a2,
                                        uint32_t a3, uint32_t b0, uint32_t b1) {
    asm volatile("mma.sync.aligned.m16n8k16.row.col.f32.f16.f16.f32 "
                 "{%0,%1,%2,%3}, {%4,%5,%6,%7}, {%8,%9}, {%0,%1,%2,%3};"
                 : "+f"(c[0]), "+f"(c[1]), "+f"(c[2]), "+f"(c[3])
                 : "r"(a0), "r"(a1), "r"(a2), "r"(a3), "r"(b0), "r"(b1));
}

// ================= Fused level kernel =================
// MODE 0: A = fp16(x0 rows)   MODE 1: A = fp16(relu(mean_p Hprev[idx_p]+b2)+xl); y->yout
// Then MSG = relu(A @ W1h^T + b1) (SMEM), Hout = MSG @ W2h^T (fp16 GMEM).
// MODE 1: gather of A-chunk kc+1 runs as a BLOCK after compute(kc) — warp-level overlap.
template<int MODE>
__global__ __launch_bounds__(THREADS, 1) void fused_level(
    const float* __restrict__ x0,
    const __half* __restrict__ Hprev, const int* __restrict__ idx,
    const float* __restrict__ b2, const float* __restrict__ xl,
    float* __restrict__ yout,
    const __half* __restrict__ W1h, const float* __restrict__ b1,
    const __half* __restrict__ W2h, __half* __restrict__ Hout)
{
    extern __shared__ __half smh[];
    const uint32_t smb = smem_u32(smh);

    const int tid = threadIdx.x;
    const int lane = tid & 31, wid = tid >> 5;
    const int g = lane >> 2, t = lane & 3;
    const int wm = (wid & 3) * 32;
    const int wn = (wid >> 2) * 64;
    const int bm = blockIdx.x * BM;

    // ---- weight cp.async mapping ----
    const int ar0 = tid >> 3, av0 = tid & 7;
    auto issueBchunk = [&](int chunk) {                 // 0-3: W1, 4-7: W2
        const int stage = chunk % BSTAGES;
        const __half* W = (chunk < 4) ? W1h : W2h;
        const __half* src = W + (size_t)ar0 * DD + (chunk & 3) * BK + av0 * 8;
        const uint32_t dst = smb + (uint32_t)(BOFF + stage * BCH + ar0 * PADH + av0 * 8) * 2u;
        #pragma unroll
        for (int i = 0; i < 4; i++)
            cp16(dst + (uint32_t)(i * 64 * PADH) * 2u, src + (size_t)(i * 64) * DD);
        CP_COMMIT();
    };

    issueBchunk(0);
    issueBchunk(1);

    // ---- gather state (MODE 1): 4 threads per node; indices packed 2/reg ----
    const int r = tid >> 2, q = tid & 3;
    const int node = bm + r;
    int pr2[8];
    if (MODE == 1) {
        const int4* ip = (const int4*)(idx + (size_t)node * KP);
        #pragma unroll
        for (int i = 0; i < 4; i++) {
            int4 v = ip[i];
            pr2[2*i]   = v.x | (v.y << 16);
            pr2[2*i+1] = v.z | (v.w << 16);
        }
    }

    // gather one full A-chunk (2 halves x 16 parents), block-style
    auto gather_chunk = [&](int kc1) {
        #pragma unroll
        for (int h = 0; h < 2; h++) {
            const int gc = kc1 * 64 + h * 32 + q * 8;
            float s[8] = {};
            #pragma unroll
            for (int b = 0; b < 4; b++) {
                uint4 gb[4];
                gb[0] = *(const uint4*)(Hprev + (size_t)(pr2[2*b]   & 0xFFFF) * DD + gc);
                gb[1] = *(const uint4*)(Hprev + (size_t)(pr2[2*b]  >> 16)     * DD + gc);
                gb[2] = *(const uint4*)(Hprev + (size_t)(pr2[2*b+1] & 0xFFFF) * DD + gc);
                gb[3] = *(const uint4*)(Hprev + (size_t)(pr2[2*b+1] >> 16)    * DD + gc);
                #pragma unroll
                for (int i = 0; i < 4; i++) {
                    const __half2* hp = (const __half2*)&gb[i];
                    #pragma unroll
                    for (int j = 0; j < 4; j++) {
                        float2 f = __half22float2(hp[j]);
                        s[2*j]   += f.x;
                        s[2*j+1] += f.y;
                    }
                }
            }
            const float inv = 1.0f / (float)KP;
            float4 bb0 = *(const float4*)(b2 + gc);
            float4 bb1 = *(const float4*)(b2 + gc + 4);
            float4 xx0 = *(const float4*)(xl + (size_t)node * DD + gc);
            float4 xx1 = *(const float4*)(xl + (size_t)node * DD + gc + 4);
            float o[8];
            o[0] = fmaxf(s[0]*inv + bb0.x, 0.f) + xx0.x;
            o[1] = fmaxf(s[1]*inv + bb0.y, 0.f) + xx0.y;
            o[2] = fmaxf(s[2]*inv + bb0.z, 0.f) + xx0.z;
            o[3] = fmaxf(s[3]*inv + bb0.w, 0.f) + xx0.w;
            o[4] = fmaxf(s[4]*inv + bb1.x, 0.f) + xx1.x;
            o[5] = fmaxf(s[5]*inv + bb1.y, 0.f) + xx1.y;
            o[6] = fmaxf(s[6]*inv + bb1.z, 0.f) + xx1.z;
            o[7] = fmaxf(s[7]*inv + bb1.w, 0.f) + xx1.w;
            __stcs((float4*)(yout + (size_t)node * DD + gc),
                   make_float4(o[0], o[1], o[2], o[3]));
            __stcs((float4*)(yout + (size_t)node * DD + gc + 4),
                   make_float4(o[4], o[5], o[6], o[7]));
            uint4 hv;
            __half2* hq = (__half2*)&hv;
            hq[0] = __float22half2_rn(make_float2(o[0], o[1]));
            hq[1] = __float22half2_rn(make_float2(o[2], o[3]));
            hq[2] = __float22half2_rn(make_float2(o[4], o[5]));
            hq[3] = __float22half2_rn(make_float2(o[6], o[7]));
            *(uint4*)(smh + kc1 * ACH + r * PADH + (h * 32 + q * 8)) = hv;
        }
    };

    // ================= Prologue: build A chunk(s) =================
    if (MODE == 0) {
        #pragma unroll
        for (int pass = 0; pass < 4; pass++) {
            const int e = tid + pass * 512;
            const int rr = e >> 4, co = (e & 15) * 16;
            const float4* xs = (const float4*)(x0 + (size_t)(bm + rr) * DD + co);
            uint4 hv[2];
            #pragma unroll
            for (int h = 0; h < 2; h++) {
                float4 v0 = xs[h * 2], v1 = xs[h * 2 + 1];
                __half2* hq = (__half2*)&hv[h];
                hq[0] = __float22half2_rn(make_float2(v0.x, v0.y));
                hq[1] = __float22half2_rn(make_float2(v0.z, v0.w));
                hq[2] = __float22half2_rn(make_float2(v1.x, v1.y));
                hq[3] = __float22half2_rn(make_float2(v1.z, v1.w));
            }
            const int ch = co >> 6, kcol = co & 63;
            *(uint4*)(smh + ch * ACH + rr * PADH + kcol) = hv[0];
            *(uint4*)(smh + ch * ACH + rr * PADH + kcol + 8) = hv[1];
        }
    } else {
        gather_chunk(0);                      // chunk 0 blocking; 1..3 under compute
    }

    // ---- ldmatrix lane mappings ----
    const int arow = lane & 15;
    const int acol = (lane >> 4) * 8;
    const int brow = (lane & 7) + ((lane >> 4) << 3);
    const int bcol = ((lane >> 3) & 1) * 8;
    uint32_t a_off[2], b_off[4];
    #pragma unroll
    for (int mf = 0; mf < 2; mf++)
        a_off[mf] = (uint32_t)((wm + mf * 16 + arow) * PADH + acol) * 2u;
    #pragma unroll
    for (int np = 0; np < 4; np++)
        b_off[np] = (uint32_t)(BOFF + (wn + np * 16 + brow) * PADH + bcol) * 2u;

    float acc[2][8][4] = {};

    auto compute = [&](int akc, int stage) {
        const uint32_t abase = smb + (uint32_t)(akc * ACH) * 2u;
        const uint32_t bbase = smb + (uint32_t)(stage * BCH) * 2u;
        #pragma unroll
        for (int ks = 0; ks < 4; ks++) {
            const uint32_t ko = ks * 32u;
            uint32_t a[2][4], b[4][4];
            #pragma unroll
            for (int mf = 0; mf < 2; mf++)
                ldsm4(a[mf][0], a[mf][1], a[mf][2], a[mf][3], abase + a_off[mf] + ko);
            #pragma unroll
            for (int np = 0; np < 4; np++)
                ldsm4(b[np][0], b[np][1], b[np][2], b[np][3], bbase + b_off[np] + ko);
            #pragma unroll
            for (int mf = 0; mf < 2; mf++)
                #pragma unroll
                for (int nf = 0; nf < 8; nf++)
                    mma_f16(acc[mf][nf],
                            a[mf][0], a[mf][1], a[mf][2], a[mf][3],
                            b[nf >> 1][(nf & 1) * 2], b[nf >> 1][(nf & 1) * 2 + 1]);
        }
    };

    // ================= Phase 1: MSG = relu(A @ W1 + b1) =================
    // One sync per chunk; gather of A-chunk kc+1 runs after compute(kc) (warp overlap).
    #pragma unroll
    for (int kc = 0; kc < NCH; kc++) {
        CP_WAIT(1);
        __syncthreads();
        issueBchunk(kc + 2);                 // chunks 2,3 (W1) then 4,5 (W2)
        compute(kc, kc % BSTAGES);
        if (MODE == 1 && kc < 3) gather_chunk(kc + 1);
    }
    __syncthreads();

    // Phase-1 epilogue: relu(acc + b1) -> MSG buffers as fp16
    #pragma unroll
    for (int mf = 0; mf < 2; mf++) {
        const int r0 = wm + mf * 16 + g;
        #pragma unroll
        for (int nf = 0; nf < 8; nf++) {
            const int col = wn + nf * 8 + 2 * t;
            const int ch = col >> 6, kcol = col & 63;
            float2 bb = *(const float2*)(b1 + col);
            float2 v0, v1;
            v0.x = fmaxf(acc[mf][nf][0] + bb.x, 0.f);
            v0.y = fmaxf(acc[mf][nf][1] + bb.y, 0.f);
            v1.x = fmaxf(acc[mf][nf][2] + bb.x, 0.f);
            v1.y = fmaxf(acc[mf][nf][3] + bb.y, 0.f);
            *(__half2*)(smh + ch * ACH + r0 * PADH + kcol) = __float22half2_rn(v0);
            *(__half2*)(smh + ch * ACH + (r0 + 8) * PADH + kcol) = __float22half2_rn(v1);
            acc[mf][nf][0] = 0.f; acc[mf][nf][1] = 0.f;
            acc[mf][nf][2] = 0.f; acc[mf][nf][3] = 0.f;
        }
    }

    // ================= Phase 2: H = MSG @ W2 =================
    #pragma unroll
    for (int kc = 0; kc < NCH; kc++) {
        if (kc < 3) { CP_WAIT(1); } else { CP_WAIT(0); }
        __syncthreads();
        if (kc < 2) issueBchunk(kc + 6);
        compute(kc, (kc + 4) % BSTAGES);
    }

    // Phase-2 epilogue: H to GMEM as fp16
    #pragma unroll
    for (int mf = 0; mf < 2; mf++) {
        const int r0 = bm + wm + mf * 16 + g;
        #pragma unroll
        for (int nf = 0; nf < 8; nf++) {
            const int col = wn + nf * 8 + 2 * t;
            float2 v0, v1;
            v0.x = acc[mf][nf][0]; v0.y = acc[mf][nf][1];
            v1.x = acc[mf][nf][2]; v1.y = acc[mf][nf][3];
            *(__half2*)(Hout + (size_t)r0 * DD + col) = __float22half2_rn(v0);
            *(__half2*)(Hout + (size_t)(r0 + 8) * DD + col) = __float22half2_rn(v1);
        }
    }
}

// ------- Final gather: y = relu(mean_p H[idx_p] + b2) + x -------
__global__ __launch_bounds__(256) void gather_epi(
    const __half* __restrict__ H, const int* __restrict__ idx,
    const float* __restrict__ b2, const float* __restrict__ x,
    float* __restrict__ y)
{
    const int node = blockIdx.x * 8 + (threadIdx.x >> 5);
    const int co = (threadIdx.x & 31) * 8;
    const int4* ip = (const int4*)(idx + (size_t)node * KP);

    int pr[KP];
    #pragma unroll
    for (int i = 0; i < 4; i++) {
        int4 v = ip[i];
        pr[i*4+0] = v.x; pr[i*4+1] = v.y; pr[i*4+2] = v.z; pr[i*4+3] = v.w;
    }
    float s[8] = {};
    #pragma unroll
    for (int p = 0; p < KP; p++) {
        uint4 u = *(const uint4*)(H + (size_t)pr[p] * DD + co);
        const __half2* hp = (const __half2*)&u;
        #pragma unroll
        for (int j = 0; j < 4; j++) {
            float2 f = __half22float2(hp[j]);
            s[j*2]   += f.x;
            s[j*2+1] += f.y;
        }
    }
    const float inv = 1.0f / (float)KP;
    float4 bb0 = *(const float4*)(b2 + co);
    float4 bb1 = *(const float4*)(b2 + co + 4);
    float4 xx0 = *(const float4*)(x + (size_t)node * DD + co);
    float4 xx1 = *(const float4*)(x + (size_t)node * DD + co + 4);
    float4* yo = (float4*)(y + (size_t)node * DD + co);
    yo[0] = make_float4(fmaxf(s[0]*inv + bb0.x, 0.f) + xx0.x,
                        fmaxf(s[1]*inv + bb0.y, 0.f) + xx0.y,
                        fmaxf(s[2]*inv + bb0.z, 0.f) + xx0.z,
                        fmaxf(s[3]*inv + bb0.w, 0.f) + xx0.w);
    yo[1] = make_float4(fmaxf(s[4]*inv + bb1.x, 0.f) + xx1.x,
                        fmaxf(s[5]*inv + bb1.y, 0.f) + xx1.y,
                        fmaxf(s[6]*inv + bb1.z, 0.f) + xx1.z,
                        fmaxf(s[7]*inv + bb1.w, 0.f) + xx1.w);
}

// ------- 256x256 transpose + fp16 rna -------
__global__ void transpose256h(const float* __restrict__ W, __half* __restrict__ Wt) {
    __shared__ float tbuf[32][33];
    const int bx = (blockIdx.x & 7) * 32;
    const int by = (blockIdx.x >> 3) * 32;
    const int x = threadIdx.x, y = threadIdx.y;
    #pragma unroll
    for (int i = 0; i < 32; i += 8)
        tbuf[y + i][x] = W[(by + y + i) * DD + bx + x];
    __syncthreads();
    #pragma unroll
    for (int i = 0; i < 32; i += 8)
        Wt[(bx + y + i) * DD + by + x] = __float2half_rn(tbuf[x][y + i]);
}

// ---------------- Launch ----------------
extern "C" void kernel_launch(void* const* d_in, const int* in_sizes, int n_in,
                              void* d_out, int out_size)
{
    const float* x   = (const float*)d_in[0];
    const int*   idx = (const int*)  d_in[1];
    const float* W1  = (const float*)d_in[2];
    const float* b1  = (const float*)d_in[3];
    const float* W2  = (const float*)d_in[4];
    const float* b2  = (const float*)d_in[5];
    float* out = (float*)d_out;

    __half *Ha, *Hb, *w1h, *w2h;
    cudaGetSymbolAddress((void**)&Ha,  g_Ha);
    cudaGetSymbolAddress((void**)&Hb,  g_Hb);
    cudaGetSymbolAddress((void**)&w1h, g_W1h);
    cudaGetSymbolAddress((void**)&w2h, g_W2h);

    cudaFuncSetAttribute(fused_level<0>, cudaFuncAttributeMaxDynamicSharedMemorySize, SMEM_BYTES);
    cudaFuncSetAttribute(fused_level<1>, cudaFuncAttributeMaxDynamicSharedMemorySize, SMEM_BYTES);

    const size_t lvl = (size_t)NN * DD;

    transpose256h<<<64, dim3(32, 8)>>>(W1, w1h);
    transpose256h<<<64, dim3(32, 8)>>>(W2, w2h);

    cudaMemcpyAsync(out, x, lvl * sizeof(float), cudaMemcpyDeviceToDevice);

    const int grid = NN / BM;   // 128 CTAs

    __half* Hbuf[2] = {Ha, Hb};

    fused_level<0><<<grid, THREADS, SMEM_BYTES>>>(
        x, nullptr, nullptr, nullptr, nullptr, nullptr, w1h, b1, w2h, Hbuf[0]);

    for (int l = 1; l <= 14; l++) {
        fused_level<1><<<grid, THREADS, SMEM_BYTES>>>(
            nullptr, Hbuf[(l - 1) & 1], idx + (size_t)(l - 1) * NN * KP,
            b2, x + (size_t)l * lvl, out + (size_t)l * lvl,
            w1h, b1, w2h, Hbuf[l & 1]);
    }

    gather_epi<<<NN / 8, 256>>>(Hbuf[14 & 1], idx + (size_t)14 * NN * KP, b2,
                                x + (size_t)15 * lvl, out + (size_t)15 * lvl);
}

// round 17
// speedup vs baseline: 1.5760x; 1.3734x over previous
#include <cuda_runtime.h>
#include <cuda_fp16.h>
#include <cstdint>

// ---------------- Problem constants ----------------
constexpr int NN = 16384;   // nodes per level
constexpr int DD = 256;     // feature dim
constexpr int KP = 16;      // in-degree
constexpr int LL = 16;      // levels

// ---------------- Fused-level tiling (fp16 operands, fp32 accum) ----------------
constexpr int THREADS = 512;
constexpr int BM = 128, BN = 256, BK = 64;
constexpr int NCH = DD / BK;                    // 4 K-chunks per GEMM
constexpr int PADH = 72;                        // halves per SMEM row (144B, conflict-free)
constexpr int ACH = BM * PADH;                  // one A/MSG chunk buffer (halves)
constexpr int BCH = BN * PADH;                  // one B stage (halves)
constexpr int MSGH = NCH * ACH;                 // 4 A chunk buffers
constexpr int BOFF = MSGH;
constexpr int BSTAGES = 3;
constexpr int SMEM_BYTES = (MSGH + BSTAGES * BCH) * 2;   // 184320 B

// ---------------- Scratch ----------------
__device__ __half g_Ha[NN * DD];
__device__ __half g_Hb[NN * DD];
__device__ __half g_W1h[DD * DD];
__device__ __half g_W2h[DD * DD];

// ---------------- Portable PTX helpers ----------------
__device__ __forceinline__ uint32_t smem_u32(const void* p) {
    uint32_t a;
    asm("{ .reg .u64 t; cvta.to.shared.u64 t, %1; cvt.u32.u64 %0, t; }" : "=r"(a) : "l"(p));
    return a;
}
__device__ __forceinline__ void cp16(uint32_t dst, const void* src) {
    asm volatile("cp.async.cg.shared.global [%0], [%1], 16;" :: "r"(dst), "l"(src));
}
#define CP_COMMIT() asm volatile("cp.async.commit_group;" ::: "memory")
#define CP_WAIT(n)  asm volatile("cp.async.wait_group %0;" :: "n"(n) : "memory")

__device__ __forceinline__ void ldsm4(uint32_t& r0, uint32_t& r1, uint32_t& r2, uint32_t& r3,
                                      uint32_t addr) {
    asm volatile("ldmatrix.sync.aligned.m8n8.x4.shared.b16 {%0,%1,%2,%3}, [%4];"
                 : "=r"(r0), "=r"(r1), "=r"(r2), "=r"(r3) : "r"(addr));
}
__device__ __forceinline__ void mma_f16(float* c, uint32_t a0, uint32_t a1, uint32_t a2,
                                        uint32_t a3, uint32_t b0, uint32_t b1) {
    asm volatile("mma.sync.aligned.m16n8k16.row.col.f32.f16.f16.f32 "
                 "{%0,%1,%2,%3}, {%4,%5,%6,%7}, {%8,%9}, {%0,%1,%2,%3};"
                 : "+f"(c[0]), "+f"(c[1]), "+f"(c[2]), "+f"(c[3])
                 : "r"(a0), "r"(a1), "r"(a2), "r"(a3), "r"(b0), "r"(b1));
}

// ================= Fused level kernel =================
// MODE 0: A = fp16(x0 rows); also streams x0 -> yout (fp32 passthrough for level 0)
// MODE 1: A = fp16(relu(mean_p Hprev[idx_p]+b2)+xl); y -> yout (streaming)
// Then MSG = relu(A @ W1h^T + b1) (SMEM), Hout = MSG @ W2h^T (fp16 GMEM).
template<int MODE>
__global__ __launch_bounds__(THREADS, 1) void fused_level(
    const float* __restrict__ x0,
    const __half* __restrict__ Hprev, const int* __restrict__ idx,
    const float* __restrict__ b2, const float* __restrict__ xl,
    float* __restrict__ yout,
    const __half* __restrict__ W1h, const float* __restrict__ b1,
    const __half* __restrict__ W2h, __half* __restrict__ Hout)
{
    extern __shared__ __half smh[];
    const uint32_t smb = smem_u32(smh);

    const int tid = threadIdx.x;
    const int lane = tid & 31, wid = tid >> 5;
    const int g = lane >> 2, t = lane & 3;
    const int wm = (wid & 3) * 32;
    const int wn = (wid >> 2) * 64;
    const int bm = blockIdx.x * BM;

    // ---- weight cp.async mapping ----
    const int ar0 = tid >> 3, av0 = tid & 7;
    auto issueBchunk = [&](int chunk) {                 // 0-3: W1, 4-7: W2
        const int stage = chunk % BSTAGES;
        const __half* W = (chunk < 4) ? W1h : W2h;
        const __half* src = W + (size_t)ar0 * DD + (chunk & 3) * BK + av0 * 8;
        const uint32_t dst = smb + (uint32_t)(BOFF + stage * BCH + ar0 * PADH + av0 * 8) * 2u;
        #pragma unroll
        for (int i = 0; i < 4; i++)
            cp16(dst + (uint32_t)(i * 64 * PADH) * 2u, src + (size_t)(i * 64) * DD);
        CP_COMMIT();
    };

    // Kick W1 chunks 0,1 so they land while the prologue runs.
    issueBchunk(0);
    issueBchunk(1);

    // ================= Prologue: build A (fp16) in MSG buffers =================
    if (MODE == 0) {
        // convert x0 rows [bm, bm+128) to fp16 operand layout; stream fp32 to yout
        #pragma unroll
        for (int pass = 0; pass < 4; pass++) {
            const int e = tid + pass * 512;             // 0..2047
            const int r = e >> 4, co = (e & 15) * 16;   // 16 cols per element
            const float4* xs = (const float4*)(x0 + (size_t)(bm + r) * DD + co);
            float4* yo = (float4*)(yout + (size_t)(bm + r) * DD + co);
            uint4 hv[2];
            #pragma unroll
            for (int h = 0; h < 2; h++) {
                float4 v0 = __ldcs(xs + h * 2), v1 = __ldcs(xs + h * 2 + 1);
                __stcs(yo + h * 2, v0);
                __stcs(yo + h * 2 + 1, v1);
                __half2* hq = (__half2*)&hv[h];
                hq[0] = __float22half2_rn(make_float2(v0.x, v0.y));
                hq[1] = __float22half2_rn(make_float2(v0.z, v0.w));
                hq[2] = __float22half2_rn(make_float2(v1.x, v1.y));
                hq[3] = __float22half2_rn(make_float2(v1.z, v1.w));
            }
            const int ch = co >> 6, kcol = co & 63;
            *(uint4*)(smh + ch * ACH + r * PADH + kcol) = hv[0];
            *(uint4*)(smh + ch * ACH + r * PADH + kcol + 8) = hv[1];
        }
    } else {
        // gather: y = relu(mean_p Hprev[idx_p] + b2) + xl ; stream yout ; A = fp16(y)
        #pragma unroll
        for (int pass = 0; pass < 8; pass++) {
            const int r = pass * 16 + (tid >> 5);       // 0..127
            const int node = bm + r;
            const int co = lane * 8;
            const int4* ip = (const int4*)(idx + (size_t)node * KP);
            int pr[KP];
            #pragma unroll
            for (int i = 0; i < 4; i++) {
                int4 v = ip[i];
                pr[i*4+0] = v.x; pr[i*4+1] = v.y; pr[i*4+2] = v.z; pr[i*4+3] = v.w;
            }
            float s[8] = {};
            #pragma unroll
            for (int p = 0; p < KP; p++) {
                uint4 u = *(const uint4*)(Hprev + (size_t)pr[p] * DD + co);
                const __half2* hp = (const __half2*)&u;
                #pragma unroll
                for (int j = 0; j < 4; j++) {
                    float2 f = __half22float2(hp[j]);
                    s[j*2]   += f.x;
                    s[j*2+1] += f.y;
                }
            }
            const float inv = 1.0f / (float)KP;
            float4 bb0 = *(const float4*)(b2 + co);
            float4 bb1 = *(const float4*)(b2 + co + 4);
            float4 xx0 = __ldcs((const float4*)(xl + (size_t)node * DD + co));
            float4 xx1 = __ldcs((const float4*)(xl + (size_t)node * DD + co + 4));
            float o[8];
            o[0] = fmaxf(s[0]*inv + bb0.x, 0.f) + xx0.x;
            o[1] = fmaxf(s[1]*inv + bb0.y, 0.f) + xx0.y;
            o[2] = fmaxf(s[2]*inv + bb0.z, 0.f) + xx0.z;
            o[3] = fmaxf(s[3]*inv + bb0.w, 0.f) + xx0.w;
            o[4] = fmaxf(s[4]*inv + bb1.x, 0.f) + xx1.x;
            o[5] = fmaxf(s[5]*inv + bb1.y, 0.f) + xx1.y;
            o[6] = fmaxf(s[6]*inv + bb1.z, 0.f) + xx1.z;
            o[7] = fmaxf(s[7]*inv + bb1.w, 0.f) + xx1.w;
            __stcs((float4*)(yout + (size_t)node * DD + co),
                   make_float4(o[0], o[1], o[2], o[3]));
            __stcs((float4*)(yout + (size_t)node * DD + co + 4),
                   make_float4(o[4], o[5], o[6], o[7]));
            uint4 hv;
            __half2* hq = (__half2*)&hv;
            hq[0] = __float22half2_rn(make_float2(o[0], o[1]));
            hq[1] = __float22half2_rn(make_float2(o[2], o[3]));
            hq[2] = __float22half2_rn(make_float2(o[4], o[5]));
            hq[3] = __float22half2_rn(make_float2(o[6], o[7]));
            const int ch = co >> 6, kcol = co & 63;
            *(uint4*)(smh + ch * ACH + r * PADH + kcol) = hv;
        }
    }

    // ---- ldmatrix lane mappings ----
    const int arow = lane & 15;
    const int acol = (lane >> 4) * 8;
    const int brow = (lane & 7) + ((lane >> 4) << 3);
    const int bcol = ((lane >> 3) & 1) * 8;
    uint32_t a_off[2], b_off[4];
    #pragma unroll
    for (int mf = 0; mf < 2; mf++)
        a_off[mf] = (uint32_t)((wm + mf * 16 + arow) * PADH + acol) * 2u;
    #pragma unroll
    for (int np = 0; np < 4; np++)
        b_off[np] = (uint32_t)(BOFF + (wn + np * 16 + brow) * PADH + bcol) * 2u;

    float acc[2][8][4] = {};

    auto compute = [&](int akc, int stage) {
        const uint32_t abase = smb + (uint32_t)(akc * ACH) * 2u;
        const uint32_t bbase = smb + (uint32_t)(stage * BCH) * 2u;
        #pragma unroll
        for (int ks = 0; ks < 4; ks++) {
            const uint32_t ko = ks * 32u;
            uint32_t a[2][4], b[4][4];
            #pragma unroll
            for (int mf = 0; mf < 2; mf++)
                ldsm4(a[mf][0], a[mf][1], a[mf][2], a[mf][3], abase + a_off[mf] + ko);
            #pragma unroll
            for (int np = 0; np < 4; np++)
                ldsm4(b[np][0], b[np][1], b[np][2], b[np][3], bbase + b_off[np] + ko);
            #pragma unroll
            for (int mf = 0; mf < 2; mf++)
                #pragma unroll
                for (int nf = 0; nf < 8; nf++)
                    mma_f16(acc[mf][nf],
                            a[mf][0], a[mf][1], a[mf][2], a[mf][3],
                            b[nf >> 1][(nf & 1) * 2], b[nf >> 1][(nf & 1) * 2 + 1]);
        }
    };

    // ================= Phase 1: MSG = relu(A @ W1 + b1) =================
    #pragma unroll
    for (int kc = 0; kc < NCH; kc++) {
        CP_WAIT(1);
        __syncthreads();
        issueBchunk(kc + 2);                 // chunks 2,3 (W1) then 4,5 (W2)
        compute(kc, kc % BSTAGES);
    }
    __syncthreads();                         // all A-reads done before MSG overwrite

    // Phase-1 epilogue: relu(acc + b1) -> MSG buffers as fp16 (A-operand layout)
    #pragma unroll
    for (int mf = 0; mf < 2; mf++) {
        const int r0 = wm + mf * 16 + g;
        #pragma unroll
        for (int nf = 0; nf < 8; nf++) {
            const int col = wn + nf * 8 + 2 * t;
            const int ch = col >> 6, kcol = col & 63;
            float2 bb = *(const float2*)(b1 + col);
            float2 v0, v1;
            v0.x = fmaxf(acc[mf][nf][0] + bb.x, 0.f);
            v0.y = fmaxf(acc[mf][nf][1] + bb.y, 0.f);
            v1.x = fmaxf(acc[mf][nf][2] + bb.x, 0.f);
            v1.y = fmaxf(acc[mf][nf][3] + bb.y, 0.f);
            *(__half2*)(smh + ch * ACH + r0 * PADH + kcol) = __float22half2_rn(v0);
            *(__half2*)(smh + ch * ACH + (r0 + 8) * PADH + kcol) = __float22half2_rn(v1);
            acc[mf][nf][0] = 0.f; acc[mf][nf][1] = 0.f;
            acc[mf][nf][2] = 0.f; acc[mf][nf][3] = 0.f;
        }
    }

    // ================= Phase 2: H = MSG @ W2 =================
    #pragma unroll
    for (int kc = 0; kc < NCH; kc++) {
        if (kc < 3) { CP_WAIT(1); } else { CP_WAIT(0); }
        __syncthreads();                     // publishes MSG writes (kc==0); stage ready
        if (kc < 2) issueBchunk(kc + 6);     // chunks 6,7 (W2)
        compute(kc, (kc + 4) % BSTAGES);
    }

    // Phase-2 epilogue: H to GMEM as fp16 (cached — next level gathers from L2)
    #pragma unroll
    for (int mf = 0; mf < 2; mf++) {
        const int r0 = bm + wm + mf * 16 + g;
        #pragma unroll
        for (int nf = 0; nf < 8; nf++) {
            const int col = wn + nf * 8 + 2 * t;
            float2 v0, v1;
            v0.x = acc[mf][nf][0]; v0.y = acc[mf][nf][1];
            v1.x = acc[mf][nf][2]; v1.y = acc[mf][nf][3];
            *(__half2*)(Hout + (size_t)r0 * DD + col) = __float22half2_rn(v0);
            *(__half2*)(Hout + (size_t)(r0 + 8) * DD + col) = __float22half2_rn(v1);
        }
    }
}

// ------- Final gather: y = relu(mean_p H[idx_p] + b2) + x -------
__global__ __launch_bounds__(256) void gather_epi(
    const __half* __restrict__ H, const int* __restrict__ idx,
    const float* __restrict__ b2, const float* __restrict__ x,
    float* __restrict__ y)
{
    const int node = blockIdx.x * 8 + (threadIdx.x >> 5);
    const int co = (threadIdx.x & 31) * 8;
    const int4* ip = (const int4*)(idx + (size_t)node * KP);

    int pr[KP];
    #pragma unroll
    for (int i = 0; i < 4; i++) {
        int4 v = ip[i];
        pr[i*4+0] = v.x; pr[i*4+1] = v.y; pr[i*4+2] = v.z; pr[i*4+3] = v.w;
    }
    float s[8] = {};
    #pragma unroll
    for (int p = 0; p < KP; p++) {
        uint4 u = *(const uint4*)(H + (size_t)pr[p] * DD + co);
        const __half2* hp = (const __half2*)&u;
        #pragma unroll
        for (int j = 0; j < 4; j++) {
            float2 f = __half22float2(hp[j]);
            s[j*2]   += f.x;
            s[j*2+1] += f.y;
        }
    }
    const float inv = 1.0f / (float)KP;
    float4 bb0 = *(const float4*)(b2 + co);
    float4 bb1 = *(const float4*)(b2 + co + 4);
    float4 xx0 = __ldcs((const float4*)(x + (size_t)node * DD + co));
    float4 xx1 = __ldcs((const float4*)(x + (size_t)node * DD + co + 4));
    __stcs((float4*)(y + (size_t)node * DD + co),
           make_float4(fmaxf(s[0]*inv + bb0.x, 0.f) + xx0.x,
                       fmaxf(s[1]*inv + bb0.y, 0.f) + xx0.y,
                       fmaxf(s[2]*inv + bb0.z, 0.f) + xx0.z,
                       fmaxf(s[3]*inv + bb0.w, 0.f) + xx0.w));
    __stcs((float4*)(y + (size_t)node * DD + co + 4),
           make_float4(fmaxf(s[4]*inv + bb1.x, 0.f) + xx1.x,
                       fmaxf(s[5]*inv + bb1.y, 0.f) + xx1.y,
                       fmaxf(s[6]*inv + bb1.z, 0.f) + xx1.z,
                       fmaxf(s[7]*inv + bb1.w, 0.f) + xx1.w));
}

// ------- 256x256 transpose + fp16 rna -------
__global__ void transpose256h(const float* __restrict__ W, __half* __restrict__ Wt) {
    __shared__ float tbuf[32][33];
    const int bx = (blockIdx.x & 7) * 32;
    const int by = (blockIdx.x >> 3) * 32;
    const int x = threadIdx.x, y = threadIdx.y;
    #pragma unroll
    for (int i = 0; i < 32; i += 8)
        tbuf[y + i][x] = W[(by + y + i) * DD + bx + x];
    __syncthreads();
    #pragma unroll
    for (int i = 0; i < 32; i += 8)
        Wt[(bx + y + i) * DD + by + x] = __float2half_rn(tbuf[x][y + i]);
}

// ---------------- Launch ----------------
extern "C" void kernel_launch(void* const* d_in, const int* in_sizes, int n_in,
                              void* d_out, int out_size)
{
    const float* x   = (const float*)d_in[0];
    const int*   idx = (const int*)  d_in[1];
    const float* W1  = (const float*)d_in[2];
    const float* b1  = (const float*)d_in[3];
    const float* W2  = (const float*)d_in[4];
    const float* b2  = (const float*)d_in[5];
    float* out = (float*)d_out;

    __half *Ha, *Hb, *w1h, *w2h;
    cudaGetSymbolAddress((void**)&Ha,  g_Ha);
    cudaGetSymbolAddress((void**)&Hb,  g_Hb);
    cudaGetSymbolAddress((void**)&w1h, g_W1h);
    cudaGetSymbolAddress((void**)&w2h, g_W2h);

    cudaFuncSetAttribute(fused_level<0>, cudaFuncAttributeMaxDynamicSharedMemorySize, SMEM_BYTES);
    cudaFuncSetAttribute(fused_level<1>, cudaFuncAttributeMaxDynamicSharedMemorySize, SMEM_BYTES);

    const size_t lvl = (size_t)NN * DD;

    transpose256h<<<64, dim3(32, 8)>>>(W1, w1h);
    transpose256h<<<64, dim3(32, 8)>>>(W2, w2h);

    const int grid = NN / BM;   // 128 CTAs

    __half* Hbuf[2] = {Ha, Hb};

    // Level 0 passthrough folded into fused<0>'s prologue (streams x0 -> out).
    // H_1 = relu(x0 @ W1 + b1) @ W2
    fused_level<0><<<grid, THREADS, SMEM_BYTES>>>(
        x, nullptr, nullptr, nullptr, nullptr, out, w1h, b1, w2h, Hbuf[0]);

    // Levels 1..14: gather prologue (y_l) + GEMMs (H_{l+1})
    for (int l = 1; l <= 14; l++) {
        fused_level<1><<<grid, THREADS, SMEM_BYTES>>>(
            nullptr, Hbuf[(l - 1) & 1], idx + (size_t)(l - 1) * NN * KP,
            b2, x + (size_t)l * lvl, out + (size_t)l * lvl,
            w1h, b1, w2h, Hbuf[l & 1]);
    }

    // Level 15: final gather
    gather_epi<<<NN / 8, 256>>>(Hbuf[14 & 1], idx + (size_t)14 * NN * KP, b2,
                                x + (size_t)15 * lvl, out + (size_t)15 * lvl);
}